// round 3
// baseline (speedup 1.0000x reference)
#include <cuda_runtime.h>
#include <cstdint>

#define D_MODEL 768
#define D3      2304
#define DFF     3072
#define NHEAD   12
#define SEQ     4096
#define BATCH   2
#define MROWS   (BATCH*SEQ)   // 8192

// ------------------------- scratch (device globals; no runtime alloc) -----
__device__ float g_qkv[MROWS * D3];      // 75.5 MB
__device__ float g_ctx[MROWS * D_MODEL]; // 25 MB
__device__ float g_y  [MROWS * D_MODEL]; // 25 MB (reused for both residual sums)
__device__ float g_x  [MROWS * D_MODEL]; // 25 MB (LN1 output)
__device__ float g_h  [MROWS * DFF];     // 100 MB

// ------------------------- generic NT GEMM: C = A(MxK) * W(NxK)^T --------
// 128x128 tile, BK=8, 256 threads, 8x8 per thread (split 4+4 fragments).
__global__ __launch_bounds__(256) void gemm_nt(
    const float* __restrict__ A, const float* __restrict__ W,
    const float* __restrict__ bias, const float* __restrict__ res,
    float* __restrict__ C, int M, int N, int K, int relu)
{
    __shared__ float As[8][128];
    __shared__ float Ws[8][128];
    const int tid = threadIdx.x;
    const int m0 = blockIdx.y * 128;
    const int n0 = blockIdx.x * 128;
    const int lr = tid >> 1;          // 0..127 row within tile
    const int lc = (tid & 1) << 2;    // 0 or 4 (k-quad)
    const int tx = tid & 15;
    const int ty = tid >> 4;

    const float* Ap = A + (size_t)(m0 + lr) * K + lc;
    const float* Wp = W + (size_t)(n0 + lr) * K + lc;

    float acc[8][8];
#pragma unroll
    for (int i = 0; i < 8; ++i)
#pragma unroll
        for (int j = 0; j < 8; ++j) acc[i][j] = 0.f;

    for (int k0 = 0; k0 < K; k0 += 8) {
        float4 av = *(const float4*)(Ap + k0);
        float4 wv = *(const float4*)(Wp + k0);
        As[lc + 0][lr] = av.x; As[lc + 1][lr] = av.y;
        As[lc + 2][lr] = av.z; As[lc + 3][lr] = av.w;
        Ws[lc + 0][lr] = wv.x; Ws[lc + 1][lr] = wv.y;
        Ws[lc + 2][lr] = wv.z; Ws[lc + 3][lr] = wv.w;
        __syncthreads();
#pragma unroll
        for (int k = 0; k < 8; ++k) {
            float a[8], b[8];
            *(float4*)(a)     = *(const float4*)(&As[k][ty * 4]);
            *(float4*)(a + 4) = *(const float4*)(&As[k][64 + ty * 4]);
            *(float4*)(b)     = *(const float4*)(&Ws[k][tx * 4]);
            *(float4*)(b + 4) = *(const float4*)(&Ws[k][64 + tx * 4]);
#pragma unroll
            for (int i = 0; i < 8; ++i)
#pragma unroll
                for (int j = 0; j < 8; ++j)
                    acc[i][j] = fmaf(a[i], b[j], acc[i][j]);
        }
        __syncthreads();
    }

    const float4 ba = *(const float4*)(bias + n0 + tx * 4);
    const float4 bb = *(const float4*)(bias + n0 + 64 + tx * 4);
#pragma unroll
    for (int i = 0; i < 8; ++i) {
        int m = m0 + ((i < 4) ? (ty * 4 + i) : (64 + ty * 4 + i - 4));
        size_t ra = (size_t)m * N + n0 + tx * 4;
        float4 va = make_float4(acc[i][0] + ba.x, acc[i][1] + ba.y,
                                acc[i][2] + ba.z, acc[i][3] + ba.w);
        float4 vb = make_float4(acc[i][4] + bb.x, acc[i][5] + bb.y,
                                acc[i][6] + bb.z, acc[i][7] + bb.w);
        if (res) {
            float4 r1 = *(const float4*)(res + ra);
            float4 r2 = *(const float4*)(res + ra + 64);
            va.x += r1.x; va.y += r1.y; va.z += r1.z; va.w += r1.w;
            vb.x += r2.x; vb.y += r2.y; vb.z += r2.z; vb.w += r2.w;
        }
        if (relu) {
            va.x = fmaxf(va.x, 0.f); va.y = fmaxf(va.y, 0.f);
            va.z = fmaxf(va.z, 0.f); va.w = fmaxf(va.w, 0.f);
            vb.x = fmaxf(vb.x, 0.f); vb.y = fmaxf(vb.y, 0.f);
            vb.z = fmaxf(vb.z, 0.f); vb.w = fmaxf(vb.w, 0.f);
        }
        *(float4*)(C + ra)      = va;
        *(float4*)(C + ra + 64) = vb;
    }
}

// ------------------------- flash attention (fp32, dh=64, Bq=Bk=64) -------
#define PADW 68
#define ATTN_SMEM ((4 * 64 * PADW + 3 * 64) * 4)   // 70400 bytes

__global__ __launch_bounds__(256) void attn_kernel(
    const float* __restrict__ qkv, float* __restrict__ ctx)
{
    extern __shared__ float sm[];
    float* Qs = sm;               // [d][q] 64x68 (transposed)
    float* Ks = Qs + 64 * PADW;   // [d][j] (transposed)
    float* Vs = Ks + 64 * PADW;   // [j][d] (natural)
    float* Ps = Vs + 64 * PADW;   // [j][q] (transposed scores/probs)
    float* ms = Ps + 64 * PADW;   // running max [64]
    float* ls = ms + 64;          // running sum [64]
    float* rs = ls + 64;          // rescale     [64]

    const int tid = threadIdx.x;
    const int bh = blockIdx.y;
    const int b = bh / NHEAD, h = bh % NHEAD;
    const int q0 = blockIdx.x * 64;
    const float* Qg = qkv + ((size_t)(b * SEQ + q0)) * D3 + h * 64;
    const float* Kg = qkv + ((size_t)(b * SEQ)) * D3 + D_MODEL + h * 64;
    const float* Vg = Kg + D_MODEL;

    const int lrow = tid >> 2;         // 0..63
    const int lcol = (tid & 3) << 2;   // 0,4,8,12

    if (tid < 64) { ms[tid] = -1e30f; ls[tid] = 0.f; }

    // load Q tile transposed: Qs[d][q]
#pragma unroll
    for (int p = 0; p < 4; ++p) {
        int d = lcol + (p << 4);
        float4 v = *(const float4*)(Qg + (size_t)lrow * D3 + d);
        Qs[(d + 0) * PADW + lrow] = v.x;
        Qs[(d + 1) * PADW + lrow] = v.y;
        Qs[(d + 2) * PADW + lrow] = v.z;
        Qs[(d + 3) * PADW + lrow] = v.w;
    }

    const int qq = tid >> 4;   // 0..15 : q-group
    const int jj = tid & 15;   // 0..15 : j-group (S phase) / d-group (PV phase)
    float accO[4][4];
#pragma unroll
    for (int i = 0; i < 4; ++i)
#pragma unroll
        for (int j = 0; j < 4; ++j) accO[i][j] = 0.f;

    for (int j0 = 0; j0 < SEQ; j0 += 64) {
        __syncthreads();   // previous PV done before overwriting K/V/Ps
#pragma unroll
        for (int p = 0; p < 4; ++p) {
            int d = lcol + (p << 4);
            size_t goff = (size_t)(j0 + lrow) * D3 + d;
            float4 kv = *(const float4*)(Kg + goff);
            Ks[(d + 0) * PADW + lrow] = kv.x;
            Ks[(d + 1) * PADW + lrow] = kv.y;
            Ks[(d + 2) * PADW + lrow] = kv.z;
            Ks[(d + 3) * PADW + lrow] = kv.w;
            float4 vv = *(const float4*)(Vg + goff);
            *(float4*)(Vs + lrow * PADW + d) = vv;
        }
        __syncthreads();

        // S[q][j] = scale * sum_d Q[q][d] K[j][d]  (4x4 per thread)
        float s[4][4];
#pragma unroll
        for (int i = 0; i < 4; ++i)
#pragma unroll
            for (int j = 0; j < 4; ++j) s[i][j] = 0.f;
#pragma unroll 8
        for (int k = 0; k < 64; ++k) {
            float qv[4], kv[4];
            *(float4*)qv = *(const float4*)(Qs + k * PADW + (qq << 2));
            *(float4*)kv = *(const float4*)(Ks + k * PADW + (jj << 2));
#pragma unroll
            for (int i = 0; i < 4; ++i)
#pragma unroll
                for (int j = 0; j < 4; ++j)
                    s[i][j] = fmaf(qv[i], kv[j], s[i][j]);
        }
        const float scale = 0.125f;   // 1/sqrt(64)
#pragma unroll
        for (int jr = 0; jr < 4; ++jr) {
            float4 w = make_float4(s[0][jr] * scale, s[1][jr] * scale,
                                   s[2][jr] * scale, s[3][jr] * scale);
            *(float4*)(Ps + (jj * 4 + jr) * PADW + qq * 4) = w;
        }
        __syncthreads();

        // online softmax: one thread per query row
        if (tid < 64) {
            float mo = ms[tid];
            float mx = mo;
#pragma unroll 8
            for (int j = 0; j < 64; ++j) mx = fmaxf(mx, Ps[j * PADW + tid]);
            float r = __expf(mo - mx);
            float sum = 0.f;
#pragma unroll 8
            for (int j = 0; j < 64; ++j) {
                float e = __expf(Ps[j * PADW + tid] - mx);
                Ps[j * PADW + tid] = e;
                sum += e;
            }
            ls[tid] = ls[tid] * r + sum;
            ms[tid] = mx;
            rs[tid] = r;
        }
        __syncthreads();

        // rescale accumulators, then O += P @ V
        float r0 = rs[qq * 4 + 0], r1 = rs[qq * 4 + 1];
        float r2 = rs[qq * 4 + 2], r3 = rs[qq * 4 + 3];
#pragma unroll
        for (int j = 0; j < 4; ++j) {
            accO[0][j] *= r0; accO[1][j] *= r1;
            accO[2][j] *= r2; accO[3][j] *= r3;
        }
#pragma unroll 8
        for (int j = 0; j < 64; ++j) {
            float pv[4], vv[4];
            *(float4*)pv = *(const float4*)(Ps + j * PADW + qq * 4);
            *(float4*)vv = *(const float4*)(Vs + j * PADW + jj * 4);
#pragma unroll
            for (int i = 0; i < 4; ++i)
#pragma unroll
                for (int c = 0; c < 4; ++c)
                    accO[i][c] = fmaf(pv[i], vv[c], accO[i][c]);
        }
    }

    float* Og = ctx + ((size_t)(b * SEQ + q0)) * D_MODEL + h * 64;
#pragma unroll
    for (int i = 0; i < 4; ++i) {
        int q = qq * 4 + i;
        float inv = 1.0f / ls[q];
        float4 o = make_float4(accO[i][0] * inv, accO[i][1] * inv,
                               accO[i][2] * inv, accO[i][3] * inv);
        *(float4*)(Og + (size_t)q * D_MODEL + jj * 4) = o;
    }
}

// ------------------------- row LayerNorm (768 cols, 256 thr/row) ---------
__global__ __launch_bounds__(256) void ln_kernel(
    const float* __restrict__ y, const float* __restrict__ g,
    const float* __restrict__ be, float* __restrict__ o)
{
    const int row = blockIdx.x;
    const float* x = y + (size_t)row * D_MODEL;
    const int t = threadIdx.x;
    float v0 = x[t], v1 = x[t + 256], v2 = x[t + 512];
    float s = v0 + v1 + v2;
    float q = v0 * v0 + v1 * v1 + v2 * v2;
#pragma unroll
    for (int off = 16; off; off >>= 1) {
        s += __shfl_xor_sync(0xffffffffu, s, off);
        q += __shfl_xor_sync(0xffffffffu, q, off);
    }
    __shared__ float ss[8], sq[8];
    __shared__ float s_mu, s_inv;
    int w = t >> 5, l = t & 31;
    if (l == 0) { ss[w] = s; sq[w] = q; }
    __syncthreads();
    if (t == 0) {
        float S = 0.f, Q = 0.f;
#pragma unroll
        for (int i = 0; i < 8; ++i) { S += ss[i]; Q += sq[i]; }
        float mu = S * (1.0f / D_MODEL);
        float var = Q * (1.0f / D_MODEL) - mu * mu;
        s_mu = mu;
        s_inv = rsqrtf(var + 1e-5f);
    }
    __syncthreads();
    float mu = s_mu, inv = s_inv;
    float* op = o + (size_t)row * D_MODEL;
    op[t]       = (v0 - mu) * inv * g[t]       + be[t];
    op[t + 256] = (v1 - mu) * inv * g[t + 256] + be[t + 256];
    op[t + 512] = (v2 - mu) * inv * g[t + 512] + be[t + 512];
}

// ------------------------- launch ----------------------------------------
extern "C" void kernel_launch(void* const* d_in, const int* in_sizes, int n_in,
                              void* d_out, int out_size)
{
    const float* src   = (const float*)d_in[0];
    const float* w_qkv = (const float*)d_in[1];
    const float* b_qkv = (const float*)d_in[2];
    const float* w_out = (const float*)d_in[3];
    const float* b_out = (const float*)d_in[4];
    const float* w1    = (const float*)d_in[5];
    const float* b1    = (const float*)d_in[6];
    const float* w2    = (const float*)d_in[7];
    const float* b2    = (const float*)d_in[8];
    const float* ln1w  = (const float*)d_in[9];
    const float* ln1b  = (const float*)d_in[10];
    const float* ln2w  = (const float*)d_in[11];
    const float* ln2b  = (const float*)d_in[12];
    float* out = (float*)d_out;

    float *qkv, *ctx, *y, *x, *hb;
    cudaGetSymbolAddress((void**)&qkv, g_qkv);
    cudaGetSymbolAddress((void**)&ctx, g_ctx);
    cudaGetSymbolAddress((void**)&y,   g_y);
    cudaGetSymbolAddress((void**)&x,   g_x);
    cudaGetSymbolAddress((void**)&hb,  g_h);

    cudaFuncSetAttribute(attn_kernel,
                         cudaFuncAttributeMaxDynamicSharedMemorySize, ATTN_SMEM);

    dim3 thr(256);
    // 1) QKV projection: [8192,2304]
    gemm_nt<<<dim3(D3 / 128, MROWS / 128), thr>>>(
        src, w_qkv, b_qkv, nullptr, qkv, MROWS, D3, D_MODEL, 0);
    // 2) flash attention -> ctx
    attn_kernel<<<dim3(SEQ / 64, BATCH * NHEAD), thr, ATTN_SMEM>>>(qkv, ctx);
    // 3) out projection + residual(src)
    gemm_nt<<<dim3(D_MODEL / 128, MROWS / 128), thr>>>(
        ctx, w_out, b_out, src, y, MROWS, D_MODEL, D_MODEL, 0);
    // 4) LN1 -> x
    ln_kernel<<<MROWS, 256>>>(y, ln1w, ln1b, x);
    // 5) FFN1 + relu
    gemm_nt<<<dim3(DFF / 128, MROWS / 128), thr>>>(
        x, w1, b1, nullptr, hb, MROWS, DFF, D_MODEL, 1);
    // 6) FFN2 + residual(x)
    gemm_nt<<<dim3(D_MODEL / 128, MROWS / 128), thr>>>(
        hb, w2, b2, x, y, MROWS, D_MODEL, DFF, 0);
    // 7) LN2 -> out
    ln_kernel<<<MROWS, 256>>>(y, ln2w, ln2b, out);
}

// round 4
// speedup vs baseline: 2.4706x; 2.4706x over previous
#include <cuda_runtime.h>
#include <cstdint>

#define D_MODEL 768
#define D3      2304
#define DFF     3072
#define NHEAD   12
#define SEQ     4096
#define BATCH   2
#define MROWS   (BATCH*SEQ)   // 8192

// ------------------------- scratch (device globals; no runtime alloc) -----
__device__ float g_qkv[MROWS * D3];      // 75.5 MB
__device__ float g_ctx[MROWS * D_MODEL]; // 25 MB
__device__ float g_y  [MROWS * D_MODEL]; // 25 MB
__device__ float g_x  [MROWS * D_MODEL]; // 25 MB
__device__ float g_h  [MROWS * DFF];     // 100 MB

// ------------------------- helpers ---------------------------------------
__device__ __forceinline__ uint32_t f2tf(float f) {
    uint32_t r;
    asm("cvt.rna.tf32.f32 %0, %1;" : "=r"(r) : "f"(f));
    return r;
}

__device__ __forceinline__ void mma_tf32(float* c, const uint32_t* a, const uint32_t* b) {
    asm volatile(
        "mma.sync.aligned.m16n8k8.row.col.f32.tf32.tf32.f32 "
        "{%0,%1,%2,%3},{%4,%5,%6,%7},{%8,%9},{%0,%1,%2,%3};"
        : "+f"(c[0]), "+f"(c[1]), "+f"(c[2]), "+f"(c[3])
        : "r"(a[0]), "r"(a[1]), "r"(a[2]), "r"(a[3]), "r"(b[0]), "r"(b[1]));
}

// ------------------------- TF32 tensor-core GEMM -------------------------
// C(MxN) = A(MxK) * W(NxK)^T + bias [+res][relu]
// 128x128 tile, BK=16, 256 threads (8 warps, warp tile 64x32).
// smem layouts [row][k], row stride 20 -> conflict-free fragment loads.
#define GPAD 20

__global__ __launch_bounds__(256) void gemm_tc(
    const float* __restrict__ A, const float* __restrict__ W,
    const float* __restrict__ bias, const float* __restrict__ res,
    float* __restrict__ C, int M, int N, int K, int relu)
{
    __shared__ uint32_t As[2][128 * GPAD];
    __shared__ uint32_t Bs[2][128 * GPAD];

    const int tid  = threadIdx.x;
    const int warp = tid >> 5;
    const int lane = tid & 31;
    const int g = lane >> 2;
    const int t = lane & 3;
    const int wm = warp >> 2;        // 0..1  -> m offset wm*64
    const int wn = warp & 3;         // 0..3  -> n offset wn*32

    const int bm0 = blockIdx.y * 128;
    const int bn0 = blockIdx.x * 128;

    // global load mapping: thread loads rows (lm, lm+64), k-quad lq
    const int lm = tid >> 2;
    const int lq = tid & 3;
    const float* Ap = A + (size_t)(bm0 + lm) * K + 4 * lq;
    const float* Wp = W + (size_t)(bn0 + lm) * K + 4 * lq;
    const size_t strA = (size_t)64 * K;

    float acc[4][4][4];
#pragma unroll
    for (int i = 0; i < 4; ++i)
#pragma unroll
        for (int j = 0; j < 4; ++j)
#pragma unroll
            for (int r = 0; r < 4; ++r) acc[i][j][r] = 0.f;

    const int NT = K / 16;

    // preload tile 0
    float4 a0 = *(const float4*)(Ap);
    float4 a1 = *(const float4*)(Ap + strA);
    float4 b0 = *(const float4*)(Wp);
    float4 b1 = *(const float4*)(Wp + strA);
    {
        uint32_t* as = As[0] + lm * GPAD + 4 * lq;
        as[0] = f2tf(a0.x); as[1] = f2tf(a0.y); as[2] = f2tf(a0.z); as[3] = f2tf(a0.w);
        uint32_t* as2 = As[0] + (lm + 64) * GPAD + 4 * lq;
        as2[0] = f2tf(a1.x); as2[1] = f2tf(a1.y); as2[2] = f2tf(a1.z); as2[3] = f2tf(a1.w);
        uint32_t* bs = Bs[0] + lm * GPAD + 4 * lq;
        bs[0] = f2tf(b0.x); bs[1] = f2tf(b0.y); bs[2] = f2tf(b0.z); bs[3] = f2tf(b0.w);
        uint32_t* bs2 = Bs[0] + (lm + 64) * GPAD + 4 * lq;
        bs2[0] = f2tf(b1.x); bs2[1] = f2tf(b1.y); bs2[2] = f2tf(b1.z); bs2[3] = f2tf(b1.w);
    }
    __syncthreads();

    for (int it = 0; it < NT; ++it) {
        float4 na0, na1, nb0, nb1;
        if (it + 1 < NT) {
            int k0 = (it + 1) * 16;
            na0 = *(const float4*)(Ap + k0);
            na1 = *(const float4*)(Ap + strA + k0);
            nb0 = *(const float4*)(Wp + k0);
            nb1 = *(const float4*)(Wp + strA + k0);
        }
        const uint32_t* as = As[it & 1];
        const uint32_t* bs = Bs[it & 1];
#pragma unroll
        for (int ks = 0; ks < 2; ++ks) {
            const int kd = ks * 8;
            uint32_t af[4][4], bf[4][2];
#pragma unroll
            for (int mt = 0; mt < 4; ++mt) {
                int m = wm * 64 + mt * 16;
                af[mt][0] = as[(m + g) * GPAD + kd + t];
                af[mt][1] = as[(m + g + 8) * GPAD + kd + t];
                af[mt][2] = as[(m + g) * GPAD + kd + t + 4];
                af[mt][3] = as[(m + g + 8) * GPAD + kd + t + 4];
            }
#pragma unroll
            for (int nt = 0; nt < 4; ++nt) {
                int n = wn * 32 + nt * 8;
                bf[nt][0] = bs[(n + g) * GPAD + kd + t];
                bf[nt][1] = bs[(n + g) * GPAD + kd + t + 4];
            }
#pragma unroll
            for (int mt = 0; mt < 4; ++mt)
#pragma unroll
                for (int nt = 0; nt < 4; ++nt)
                    mma_tf32(acc[mt][nt], af[mt], bf[nt]);
        }
        if (it + 1 < NT) {
            uint32_t* das = As[(it + 1) & 1] + lm * GPAD + 4 * lq;
            das[0] = f2tf(na0.x); das[1] = f2tf(na0.y); das[2] = f2tf(na0.z); das[3] = f2tf(na0.w);
            uint32_t* das2 = As[(it + 1) & 1] + (lm + 64) * GPAD + 4 * lq;
            das2[0] = f2tf(na1.x); das2[1] = f2tf(na1.y); das2[2] = f2tf(na1.z); das2[3] = f2tf(na1.w);
            uint32_t* dbs = Bs[(it + 1) & 1] + lm * GPAD + 4 * lq;
            dbs[0] = f2tf(nb0.x); dbs[1] = f2tf(nb0.y); dbs[2] = f2tf(nb0.z); dbs[3] = f2tf(nb0.w);
            uint32_t* dbs2 = Bs[(it + 1) & 1] + (lm + 64) * GPAD + 4 * lq;
            dbs2[0] = f2tf(nb1.x); dbs2[1] = f2tf(nb1.y); dbs2[2] = f2tf(nb1.z); dbs2[3] = f2tf(nb1.w);
        }
        __syncthreads();
    }

    // epilogue: bias + optional residual + relu, float2 stores
#pragma unroll
    for (int nt = 0; nt < 4; ++nt) {
        const int n = bn0 + wn * 32 + nt * 8 + 2 * t;
        const float2 bv = *(const float2*)(bias + n);
#pragma unroll
        for (int mt = 0; mt < 4; ++mt) {
            const int r0 = bm0 + wm * 64 + mt * 16 + g;
            const int r1 = r0 + 8;
            float2 v0 = make_float2(acc[mt][nt][0] + bv.x, acc[mt][nt][1] + bv.y);
            float2 v1 = make_float2(acc[mt][nt][2] + bv.x, acc[mt][nt][3] + bv.y);
            if (res) {
                float2 q0 = *(const float2*)(res + (size_t)r0 * N + n);
                float2 q1 = *(const float2*)(res + (size_t)r1 * N + n);
                v0.x += q0.x; v0.y += q0.y; v1.x += q1.x; v1.y += q1.y;
            }
            if (relu) {
                v0.x = fmaxf(v0.x, 0.f); v0.y = fmaxf(v0.y, 0.f);
                v1.x = fmaxf(v1.x, 0.f); v1.y = fmaxf(v1.y, 0.f);
            }
            *(float2*)(C + (size_t)r0 * N + n) = v0;
            *(float2*)(C + (size_t)r1 * N + n) = v1;
        }
    }
}

// ------------------------- TF32 flash attention --------------------------
// Bq=Bk=64, dh=64. QK^T and PV via m16n8k8 mma, softmax fp32.
#define PQ 68   // pad for [m][k]-style reads (4g+t)
#define PV 72   // pad for [k][n]-style reads (8t+g)
#define ATTN_SMEM ((3 * 64 * PQ + 64 * PV + 3 * 64) * 4)

__global__ __launch_bounds__(256) void attn_tc(
    const float* __restrict__ qkv, float* __restrict__ ctx)
{
    extern __shared__ float sm[];
    float* Qs = sm;                 // [q][d] pad 68
    float* Ks = Qs + 64 * PQ;       // [j][d] pad 68
    float* Ps = Ks + 64 * PQ;       // [q][j] pad 68
    float* Vs = Ps + 64 * PQ;       // [j][d] pad 72
    float* ms = Vs + 64 * PV;
    float* ls = ms + 64;
    float* rs = ls + 64;
    uint32_t* Qu = (uint32_t*)Qs;
    uint32_t* Ku = (uint32_t*)Ks;
    uint32_t* Pu = (uint32_t*)Ps;
    uint32_t* Vu = (uint32_t*)Vs;

    const int tid  = threadIdx.x;
    const int lane = tid & 31;
    const int warp = tid >> 5;
    const int g = lane >> 2;
    const int t = lane & 3;
    const int wq = warp >> 1;     // 0..3 -> q offset wq*16
    const int wj = warp & 1;      // 0..1 -> j/d offset wj*32
    const int q0w = wq * 16;

    const int bh = blockIdx.y;
    const int b = bh / NHEAD, h = bh % NHEAD;
    const int q0 = blockIdx.x * 64;
    const float* Qg = qkv + ((size_t)(b * SEQ + q0)) * D3 + h * 64;
    const float* Kg = qkv + ((size_t)(b * SEQ)) * D3 + D_MODEL + h * 64;
    const float* Vg = Kg + D_MODEL;

    if (tid < 64) { ms[tid] = -1e30f; ls[tid] = 0.f; }

    // load Q tile (tf32-rounded)
    {
        const int jr = tid >> 2;
        const int dc = (tid & 3) * 4;
#pragma unroll
        for (int p = 0; p < 4; ++p) {
            int d = dc + p * 16;
            float4 v = *(const float4*)(Qg + (size_t)jr * D3 + d);
            uint32_t* dst = Qu + jr * PQ + d;
            dst[0] = f2tf(v.x); dst[1] = f2tf(v.y);
            dst[2] = f2tf(v.z); dst[3] = f2tf(v.w);
        }
    }

    float accO[4][4];
#pragma unroll
    for (int i = 0; i < 4; ++i)
#pragma unroll
        for (int j = 0; j < 4; ++j) accO[i][j] = 0.f;

    for (int j0 = 0; j0 < SEQ; j0 += 64) {
        __syncthreads();   // prior PV done before overwriting K/V/Ps
        {
            const int jr = tid >> 2;
            const int dc = (tid & 3) * 4;
#pragma unroll
            for (int p = 0; p < 4; ++p) {
                int d = dc + p * 16;
                size_t go = (size_t)(j0 + jr) * D3 + d;
                float4 kv = *(const float4*)(Kg + go);
                uint32_t* kd = Ku + jr * PQ + d;
                kd[0] = f2tf(kv.x); kd[1] = f2tf(kv.y);
                kd[2] = f2tf(kv.z); kd[3] = f2tf(kv.w);
                float4 vv = *(const float4*)(Vg + go);
                uint32_t* vd = Vu + jr * PV + d;
                vd[0] = f2tf(vv.x); vd[1] = f2tf(vv.y);
                vd[2] = f2tf(vv.z); vd[3] = f2tf(vv.w);
            }
        }
        __syncthreads();

        // S = Q K^T  (warp: 16q x 32j)
        float sacc[4][4];
#pragma unroll
        for (int i = 0; i < 4; ++i)
#pragma unroll
            for (int j = 0; j < 4; ++j) sacc[i][j] = 0.f;
#pragma unroll
        for (int ks = 0; ks < 8; ++ks) {
            const int kd = ks * 8;
            uint32_t af[4];
            af[0] = Qu[(q0w + g) * PQ + kd + t];
            af[1] = Qu[(q0w + g + 8) * PQ + kd + t];
            af[2] = Qu[(q0w + g) * PQ + kd + t + 4];
            af[3] = Qu[(q0w + g + 8) * PQ + kd + t + 4];
#pragma unroll
            for (int nt = 0; nt < 4; ++nt) {
                int jn = wj * 32 + nt * 8;
                uint32_t bf[2];
                bf[0] = Ku[(jn + g) * PQ + kd + t];
                bf[1] = Ku[(jn + g) * PQ + kd + t + 4];
                mma_tf32(sacc[nt], af, bf);
            }
        }
        const float scale = 0.125f;
#pragma unroll
        for (int nt = 0; nt < 4; ++nt) {
            int j = wj * 32 + nt * 8 + 2 * t;
            *(float2*)(Ps + (q0w + g) * PQ + j) =
                make_float2(sacc[nt][0] * scale, sacc[nt][1] * scale);
            *(float2*)(Ps + (q0w + g + 8) * PQ + j) =
                make_float2(sacc[nt][2] * scale, sacc[nt][3] * scale);
        }
        __syncthreads();

        // online softmax: 4 threads per query row, 16 cols each
        {
            const int q = tid >> 2;
            const int pt = tid & 3;
            float* Pq = Ps + q * PQ + pt * 16;
            float mo = ms[q];
            float mx = -1e30f;
#pragma unroll
            for (int i = 0; i < 16; ++i) mx = fmaxf(mx, Pq[i]);
            mx = fmaxf(mx, __shfl_xor_sync(0xffffffffu, mx, 1));
            mx = fmaxf(mx, __shfl_xor_sync(0xffffffffu, mx, 2));
            mx = fmaxf(mx, mo);
            float sum = 0.f;
            uint32_t* Pqi = (uint32_t*)Pq;
#pragma unroll
            for (int i = 0; i < 16; ++i) {
                float e = __expf(Pq[i] - mx);
                sum += e;
                Pqi[i] = f2tf(e);      // tf32 bits for the PV mma
            }
            sum += __shfl_xor_sync(0xffffffffu, sum, 1);
            sum += __shfl_xor_sync(0xffffffffu, sum, 2);
            if (pt == 0) {
                float r = __expf(mo - mx);
                ls[q] = ls[q] * r + sum;
                ms[q] = mx;
                rs[q] = r;
            }
        }
        __syncthreads();

        // rescale, then O += P V  (warp: 16q x 32d)
        const float rlo = rs[q0w + g];
        const float rhi = rs[q0w + g + 8];
#pragma unroll
        for (int nt = 0; nt < 4; ++nt) {
            accO[nt][0] *= rlo; accO[nt][1] *= rlo;
            accO[nt][2] *= rhi; accO[nt][3] *= rhi;
        }
#pragma unroll
        for (int ks = 0; ks < 8; ++ks) {
            const int kj = ks * 8;
            uint32_t af[4];
            af[0] = Pu[(q0w + g) * PQ + kj + t];
            af[1] = Pu[(q0w + g + 8) * PQ + kj + t];
            af[2] = Pu[(q0w + g) * PQ + kj + t + 4];
            af[3] = Pu[(q0w + g + 8) * PQ + kj + t + 4];
#pragma unroll
            for (int nt = 0; nt < 4; ++nt) {
                int dn = wj * 32 + nt * 8;
                uint32_t bf[2];
                bf[0] = Vu[(kj + t) * PV + dn + g];
                bf[1] = Vu[(kj + t + 4) * PV + dn + g];
                mma_tf32(accO[nt], af, bf);
            }
        }
    }

    // write output
    const float ilo = 1.0f / ls[q0w + g];
    const float ihi = 1.0f / ls[q0w + g + 8];
    float* Og = ctx + ((size_t)(b * SEQ + q0)) * D_MODEL + h * 64;
#pragma unroll
    for (int nt = 0; nt < 4; ++nt) {
        int d = wj * 32 + nt * 8 + 2 * t;
        *(float2*)(Og + (size_t)(q0w + g) * D_MODEL + d) =
            make_float2(accO[nt][0] * ilo, accO[nt][1] * ilo);
        *(float2*)(Og + (size_t)(q0w + g + 8) * D_MODEL + d) =
            make_float2(accO[nt][2] * ihi, accO[nt][3] * ihi);
    }
}

// ------------------------- row LayerNorm ---------------------------------
__global__ __launch_bounds__(256) void ln_kernel(
    const float* __restrict__ y, const float* __restrict__ g,
    const float* __restrict__ be, float* __restrict__ o)
{
    const int row = blockIdx.x;
    const float* x = y + (size_t)row * D_MODEL;
    const int t = threadIdx.x;
    float v0 = x[t], v1 = x[t + 256], v2 = x[t + 512];
    float s = v0 + v1 + v2;
    float q = v0 * v0 + v1 * v1 + v2 * v2;
#pragma unroll
    for (int off = 16; off; off >>= 1) {
        s += __shfl_xor_sync(0xffffffffu, s, off);
        q += __shfl_xor_sync(0xffffffffu, q, off);
    }
    __shared__ float ss[8], sq[8];
    __shared__ float s_mu, s_inv;
    int w = t >> 5, l = t & 31;
    if (l == 0) { ss[w] = s; sq[w] = q; }
    __syncthreads();
    if (t == 0) {
        float S = 0.f, Q = 0.f;
#pragma unroll
        for (int i = 0; i < 8; ++i) { S += ss[i]; Q += sq[i]; }
        float mu = S * (1.0f / D_MODEL);
        float var = Q * (1.0f / D_MODEL) - mu * mu;
        s_mu = mu;
        s_inv = rsqrtf(var + 1e-5f);
    }
    __syncthreads();
    float mu = s_mu, inv = s_inv;
    float* op = o + (size_t)row * D_MODEL;
    op[t]       = (v0 - mu) * inv * g[t]       + be[t];
    op[t + 256] = (v1 - mu) * inv * g[t + 256] + be[t + 256];
    op[t + 512] = (v2 - mu) * inv * g[t + 512] + be[t + 512];
}

// ------------------------- launch ----------------------------------------
extern "C" void kernel_launch(void* const* d_in, const int* in_sizes, int n_in,
                              void* d_out, int out_size)
{
    const float* src   = (const float*)d_in[0];
    const float* w_qkv = (const float*)d_in[1];
    const float* b_qkv = (const float*)d_in[2];
    const float* w_out = (const float*)d_in[3];
    const float* b_out = (const float*)d_in[4];
    const float* w1    = (const float*)d_in[5];
    const float* b1    = (const float*)d_in[6];
    const float* w2    = (const float*)d_in[7];
    const float* b2    = (const float*)d_in[8];
    const float* ln1w  = (const float*)d_in[9];
    const float* ln1b  = (const float*)d_in[10];
    const float* ln2w  = (const float*)d_in[11];
    const float* ln2b  = (const float*)d_in[12];
    float* out = (float*)d_out;

    float *qkv, *ctx, *y, *x, *hb;
    cudaGetSymbolAddress((void**)&qkv, g_qkv);
    cudaGetSymbolAddress((void**)&ctx, g_ctx);
    cudaGetSymbolAddress((void**)&y,   g_y);
    cudaGetSymbolAddress((void**)&x,   g_x);
    cudaGetSymbolAddress((void**)&hb,  g_h);

    cudaFuncSetAttribute(attn_tc,
                         cudaFuncAttributeMaxDynamicSharedMemorySize, ATTN_SMEM);

    dim3 thr(256);
    // 1) QKV projection
    gemm_tc<<<dim3(D3 / 128, MROWS / 128), thr>>>(
        src, w_qkv, b_qkv, nullptr, qkv, MROWS, D3, D_MODEL, 0);
    // 2) flash attention
    attn_tc<<<dim3(SEQ / 64, BATCH * NHEAD), thr, ATTN_SMEM>>>(qkv, ctx);
    // 3) out projection + residual(src)
    gemm_tc<<<dim3(D_MODEL / 128, MROWS / 128), thr>>>(
        ctx, w_out, b_out, src, y, MROWS, D_MODEL, D_MODEL, 0);
    // 4) LN1
    ln_kernel<<<MROWS, 256>>>(y, ln1w, ln1b, x);
    // 5) FFN1 + relu
    gemm_tc<<<dim3(DFF / 128, MROWS / 128), thr>>>(
        x, w1, b1, nullptr, hb, MROWS, DFF, D_MODEL, 1);
    // 6) FFN2 + residual(x)
    gemm_tc<<<dim3(D_MODEL / 128, MROWS / 128), thr>>>(
        hb, w2, b2, x, y, MROWS, D_MODEL, DFF, 0);
    // 7) LN2
    ln_kernel<<<MROWS, 256>>>(y, ln2w, ln2b, out);
}

// round 5
// speedup vs baseline: 2.9062x; 1.1763x over previous
#include <cuda_runtime.h>
#include <cuda_bf16.h>
#include <cstdint>

#define D_MODEL 768
#define D3      2304
#define DFF     3072
#define NHEAD   12
#define SEQ     4096
#define BATCH   2
#define MROWS   (BATCH*SEQ)   // 8192

// ------------------------- scratch (device globals; no runtime alloc) -----
__device__ float g_qkv[MROWS * D3];
__device__ float g_ctx[MROWS * D_MODEL];
__device__ float g_y  [MROWS * D_MODEL];
__device__ float g_x  [MROWS * D_MODEL];
__device__ float g_h  [MROWS * DFF];

// ------------------------- helpers ---------------------------------------
// pack two fp32 -> bf16x2 word, lo = first arg (even-k element)
__device__ __forceinline__ uint32_t pack2(float lo, float hi) {
    uint32_t r;
    asm("cvt.rn.bf16x2.f32 %0, %2, %1;" : "=r"(r) : "f"(lo), "f"(hi));
    return r;
}

__device__ __forceinline__ void mma_bf16(float* c, const uint32_t* a, const uint32_t* b) {
    asm volatile(
        "mma.sync.aligned.m16n8k16.row.col.f32.bf16.bf16.f32 "
        "{%0,%1,%2,%3},{%4,%5,%6,%7},{%8,%9},{%0,%1,%2,%3};"
        : "+f"(c[0]), "+f"(c[1]), "+f"(c[2]), "+f"(c[3])
        : "r"(a[0]), "r"(a[1]), "r"(a[2]), "r"(a[3]), "r"(b[0]), "r"(b[1]));
}

// ------------------------- BF16 tensor-core GEMM -------------------------
// C(MxN) = A(MxK) * W(NxK)^T + bias [+res][relu]
// 128x128 tile, BK=32 elements (16 words), 256 threads, warp tile 64x32.
// smem [row][k-pair-word], row stride 20 words -> conflict-free fragments.
#define GPW 20

__global__ __launch_bounds__(256) void gemm_tc(
    const float* __restrict__ A, const float* __restrict__ W,
    const float* __restrict__ bias, const float* __restrict__ res,
    float* __restrict__ C, int M, int N, int K, int relu)
{
    __shared__ uint32_t As[2][128 * GPW];
    __shared__ uint32_t Bs[2][128 * GPW];

    const int tid  = threadIdx.x;
    const int warp = tid >> 5;
    const int lane = tid & 31;
    const int g = lane >> 2;
    const int t = lane & 3;
    const int wm = warp >> 2;        // m offset wm*64
    const int wn = warp & 3;         // n offset wn*32

    const int bm0 = blockIdx.y * 128;
    const int bn0 = blockIdx.x * 128;

    // global load: lm = row (0..31, +32r), lq = k-quad (4 floats)
    const int lm = tid >> 3;
    const int lq = tid & 7;
    const float* Ap = A + (size_t)(bm0 + lm) * K + 4 * lq;
    const float* Wp = W + (size_t)(bn0 + lm) * K + 4 * lq;
    const size_t rstr = (size_t)32 * K;

    float acc[4][4][4];
#pragma unroll
    for (int i = 0; i < 4; ++i)
#pragma unroll
        for (int j = 0; j < 4; ++j)
#pragma unroll
            for (int r = 0; r < 4; ++r) acc[i][j][r] = 0.f;

    const int NT = K / 32;

    // preload tile 0
    float4 pa[4], pb[4];
#pragma unroll
    for (int r = 0; r < 4; ++r) {
        pa[r] = *(const float4*)(Ap + rstr * r);
        pb[r] = *(const float4*)(Wp + rstr * r);
    }
#pragma unroll
    for (int r = 0; r < 4; ++r) {
        uint32_t* as = As[0] + (lm + 32 * r) * GPW + 2 * lq;
        as[0] = pack2(pa[r].x, pa[r].y); as[1] = pack2(pa[r].z, pa[r].w);
        uint32_t* bs = Bs[0] + (lm + 32 * r) * GPW + 2 * lq;
        bs[0] = pack2(pb[r].x, pb[r].y); bs[1] = pack2(pb[r].z, pb[r].w);
    }
    __syncthreads();

    for (int it = 0; it < NT; ++it) {
        if (it + 1 < NT) {
            const int k0 = (it + 1) * 32;
#pragma unroll
            for (int r = 0; r < 4; ++r) {
                pa[r] = *(const float4*)(Ap + rstr * r + k0);
                pb[r] = *(const float4*)(Wp + rstr * r + k0);
            }
        }
        const uint32_t* as = As[it & 1];
        const uint32_t* bs = Bs[it & 1];
#pragma unroll
        for (int ks = 0; ks < 2; ++ks) {
            const int kd = ks * 8;
            uint32_t af[4][4], bf[4][2];
#pragma unroll
            for (int mt = 0; mt < 4; ++mt) {
                int m = wm * 64 + mt * 16;
                af[mt][0] = as[(m + g) * GPW + kd + t];
                af[mt][1] = as[(m + g + 8) * GPW + kd + t];
                af[mt][2] = as[(m + g) * GPW + kd + t + 4];
                af[mt][3] = as[(m + g + 8) * GPW + kd + t + 4];
            }
#pragma unroll
            for (int nt = 0; nt < 4; ++nt) {
                int n = wn * 32 + nt * 8;
                bf[nt][0] = bs[(n + g) * GPW + kd + t];
                bf[nt][1] = bs[(n + g) * GPW + kd + t + 4];
            }
#pragma unroll
            for (int mt = 0; mt < 4; ++mt)
#pragma unroll
                for (int nt = 0; nt < 4; ++nt)
                    mma_bf16(acc[mt][nt], af[mt], bf[nt]);
        }
        if (it + 1 < NT) {
            uint32_t* das = As[(it + 1) & 1];
            uint32_t* dbs = Bs[(it + 1) & 1];
#pragma unroll
            for (int r = 0; r < 4; ++r) {
                uint32_t* a2 = das + (lm + 32 * r) * GPW + 2 * lq;
                a2[0] = pack2(pa[r].x, pa[r].y); a2[1] = pack2(pa[r].z, pa[r].w);
                uint32_t* b2 = dbs + (lm + 32 * r) * GPW + 2 * lq;
                b2[0] = pack2(pb[r].x, pb[r].y); b2[1] = pack2(pb[r].z, pb[r].w);
            }
        }
        __syncthreads();
    }

    // epilogue: bias + optional residual + relu
#pragma unroll
    for (int nt = 0; nt < 4; ++nt) {
        const int n = bn0 + wn * 32 + nt * 8 + 2 * t;
        const float2 bv = *(const float2*)(bias + n);
#pragma unroll
        for (int mt = 0; mt < 4; ++mt) {
            const int r0 = bm0 + wm * 64 + mt * 16 + g;
            const int r1 = r0 + 8;
            float2 v0 = make_float2(acc[mt][nt][0] + bv.x, acc[mt][nt][1] + bv.y);
            float2 v1 = make_float2(acc[mt][nt][2] + bv.x, acc[mt][nt][3] + bv.y);
            if (res) {
                float2 q0 = *(const float2*)(res + (size_t)r0 * N + n);
                float2 q1 = *(const float2*)(res + (size_t)r1 * N + n);
                v0.x += q0.x; v0.y += q0.y; v1.x += q1.x; v1.y += q1.y;
            }
            if (relu) {
                v0.x = fmaxf(v0.x, 0.f); v0.y = fmaxf(v0.y, 0.f);
                v1.x = fmaxf(v1.x, 0.f); v1.y = fmaxf(v1.y, 0.f);
            }
            *(float2*)(C + (size_t)r0 * N + n) = v0;
            *(float2*)(C + (size_t)r1 * N + n) = v1;
        }
    }
}

// ------------------------- BF16 flash attention --------------------------
// Bq=Bk=64, dh=64. QK^T and PV via m16n8k16 bf16 mma, softmax fp32.
#define AW 36             // padded words per row for Q/K/V/P (32 used)
#define SSP 68            // fp32 score row pad
// word offsets in dynamic smem
#define OFF_Q  0
#define OFF_K  (64 * AW)
#define OFF_V  (2 * 64 * AW)
#define OFF_SS (3 * 64 * AW)          // fp32 [64][68]
#define OFF_P  (OFF_SS + 64 * SSP)
#define OFF_MS (OFF_P + 64 * AW)
#define ATTN_WORDS (OFF_MS + 3 * 64)
#define ATTN_SMEM (ATTN_WORDS * 4)

__global__ __launch_bounds__(256) void attn_tc(
    const float* __restrict__ qkv, float* __restrict__ ctx)
{
    extern __shared__ uint32_t smu[];
    uint32_t* Qu = smu + OFF_Q;       // [q][d-pair]
    uint32_t* Ku = smu + OFF_K;       // [j][d-pair]
    uint32_t* Vu = smu + OFF_V;       // [d][j-pair]  (transposed)
    float*    Ss = (float*)(smu + OFF_SS);  // [q][j] fp32
    uint32_t* Pu = smu + OFF_P;       // [q][j-pair]
    float*    ms = (float*)(smu + OFF_MS);
    float*    ls = ms + 64;
    float*    rs = ls + 64;

    const int tid  = threadIdx.x;
    const int lane = tid & 31;
    const int warp = tid >> 5;
    const int g = lane >> 2;
    const int t = lane & 3;
    const int wq = warp >> 1;       // q offset wq*16
    const int wj = warp & 1;        // j/d offset wj*32
    const int q0w = wq * 16;

    const int bh = blockIdx.y;
    const int b = bh / NHEAD, h = bh % NHEAD;
    const int q0 = blockIdx.x * 64;
    const float* Qg = qkv + ((size_t)(b * SEQ + q0)) * D3 + h * 64;
    const float* Kg = qkv + ((size_t)(b * SEQ)) * D3 + D_MODEL + h * 64;
    const float* Vg = Kg + D_MODEL;

    if (tid < 64) { ms[tid] = -1e30f; ls[tid] = 0.f; }

    // load Q tile (bf16 pairs along d)
    {
        const int jr = tid >> 2;
        const int dc = (tid & 3) * 4;
#pragma unroll
        for (int p = 0; p < 4; ++p) {
            int d = dc + p * 16;
            float4 v = *(const float4*)(Qg + (size_t)jr * D3 + d);
            uint32_t* dst = Qu + jr * AW + (d >> 1);
            dst[0] = pack2(v.x, v.y);
            dst[1] = pack2(v.z, v.w);
        }
    }

    float accO[4][4];
#pragma unroll
    for (int i = 0; i < 4; ++i)
#pragma unroll
        for (int j = 0; j < 4; ++j) accO[i][j] = 0.f;

    for (int j0 = 0; j0 < SEQ; j0 += 64) {
        __syncthreads();    // prior PV done before overwriting K/V
        // K: [j][d-pair]
        {
            const int jr = tid >> 2;
            const int dc = (tid & 3) * 4;
#pragma unroll
            for (int p = 0; p < 4; ++p) {
                int d = dc + p * 16;
                float4 kv = *(const float4*)(Kg + (size_t)(j0 + jr) * D3 + d);
                uint32_t* kd = Ku + jr * AW + (d >> 1);
                kd[0] = pack2(kv.x, kv.y);
                kd[1] = pack2(kv.z, kv.w);
            }
        }
        // V transposed: [d][j-pair]
        {
            const int jp = tid & 31;        // j-pair index
            const int dq = tid >> 5;        // 0..7
#pragma unroll
            for (int p = 0; p < 2; ++p) {
                int d0 = 4 * dq + 32 * p;
                size_t go = (size_t)(j0 + 2 * jp) * D3 + d0;
                float4 v0 = *(const float4*)(Vg + go);
                float4 v1 = *(const float4*)(Vg + go + D3);
                Vu[(d0 + 0) * AW + jp] = pack2(v0.x, v1.x);
                Vu[(d0 + 1) * AW + jp] = pack2(v0.y, v1.y);
                Vu[(d0 + 2) * AW + jp] = pack2(v0.z, v1.z);
                Vu[(d0 + 3) * AW + jp] = pack2(v0.w, v1.w);
            }
        }
        __syncthreads();

        // S = Q K^T (warp: 16q x 32j), dh=64 -> 4 k16 steps
        float sacc[4][4];
#pragma unroll
        for (int i = 0; i < 4; ++i)
#pragma unroll
            for (int j = 0; j < 4; ++j) sacc[i][j] = 0.f;
#pragma unroll
        for (int ks = 0; ks < 4; ++ks) {
            const int kd = ks * 8;
            uint32_t af[4];
            af[0] = Qu[(q0w + g) * AW + kd + t];
            af[1] = Qu[(q0w + g + 8) * AW + kd + t];
            af[2] = Qu[(q0w + g) * AW + kd + t + 4];
            af[3] = Qu[(q0w + g + 8) * AW + kd + t + 4];
#pragma unroll
            for (int nt = 0; nt < 4; ++nt) {
                int jn = wj * 32 + nt * 8;
                uint32_t bf[2];
                bf[0] = Ku[(jn + g) * AW + kd + t];
                bf[1] = Ku[(jn + g) * AW + kd + t + 4];
                mma_bf16(sacc[nt], af, bf);
            }
        }
        const float scale = 0.125f;
#pragma unroll
        for (int nt = 0; nt < 4; ++nt) {
            int j = wj * 32 + nt * 8 + 2 * t;
            *(float2*)(Ss + (q0w + g) * SSP + j) =
                make_float2(sacc[nt][0] * scale, sacc[nt][1] * scale);
            *(float2*)(Ss + (q0w + g + 8) * SSP + j) =
                make_float2(sacc[nt][2] * scale, sacc[nt][3] * scale);
        }
        __syncthreads();

        // online softmax: 4 threads/row, 16 cols each; write bf16 P pairs
        {
            const int q = tid >> 2;
            const int pt = tid & 3;
            const float* Sq = Ss + q * SSP + pt * 16;
            float mo = ms[q];
            float mx = -1e30f;
#pragma unroll
            for (int i = 0; i < 16; ++i) mx = fmaxf(mx, Sq[i]);
            mx = fmaxf(mx, __shfl_xor_sync(0xffffffffu, mx, 1));
            mx = fmaxf(mx, __shfl_xor_sync(0xffffffffu, mx, 2));
            mx = fmaxf(mx, mo);
            float sum = 0.f;
            uint32_t* Pq = Pu + q * AW + pt * 8;
#pragma unroll
            for (int i = 0; i < 8; ++i) {
                float e0 = __expf(Sq[2 * i]     - mx);
                float e1 = __expf(Sq[2 * i + 1] - mx);
                sum += e0 + e1;
                Pq[i] = pack2(e0, e1);
            }
            sum += __shfl_xor_sync(0xffffffffu, sum, 1);
            sum += __shfl_xor_sync(0xffffffffu, sum, 2);
            if (pt == 0) {
                float r = __expf(mo - mx);
                ls[q] = ls[q] * r + sum;
                ms[q] = mx;
                rs[q] = r;
            }
        }
        __syncthreads();

        // rescale, then O += P V (warp: 16q x 32d), 4 k16 steps over j
        const float rlo = rs[q0w + g];
        const float rhi = rs[q0w + g + 8];
#pragma unroll
        for (int nt = 0; nt < 4; ++nt) {
            accO[nt][0] *= rlo; accO[nt][1] *= rlo;
            accO[nt][2] *= rhi; accO[nt][3] *= rhi;
        }
#pragma unroll
        for (int ks = 0; ks < 4; ++ks) {
            const int kw = ks * 8;
            uint32_t af[4];
            af[0] = Pu[(q0w + g) * AW + kw + t];
            af[1] = Pu[(q0w + g + 8) * AW + kw + t];
            af[2] = Pu[(q0w + g) * AW + kw + t + 4];
            af[3] = Pu[(q0w + g + 8) * AW + kw + t + 4];
#pragma unroll
            for (int nt = 0; nt < 4; ++nt) {
                int dn = wj * 32 + nt * 8;
                uint32_t bf[2];
                bf[0] = Vu[(dn + g) * AW + kw + t];
                bf[1] = Vu[(dn + g) * AW + kw + t + 4];
                mma_bf16(accO[nt], af, bf);
            }
        }
    }

    // write output
    const float ilo = 1.0f / ls[q0w + g];
    const float ihi = 1.0f / ls[q0w + g + 8];
    float* Og = ctx + ((size_t)(b * SEQ + q0)) * D_MODEL + h * 64;
#pragma unroll
    for (int nt = 0; nt < 4; ++nt) {
        int d = wj * 32 + nt * 8 + 2 * t;
        *(float2*)(Og + (size_t)(q0w + g) * D_MODEL + d) =
            make_float2(accO[nt][0] * ilo, accO[nt][1] * ilo);
        *(float2*)(Og + (size_t)(q0w + g + 8) * D_MODEL + d) =
            make_float2(accO[nt][2] * ihi, accO[nt][3] * ihi);
    }
}

// ------------------------- row LayerNorm ---------------------------------
__global__ __launch_bounds__(256) void ln_kernel(
    const float* __restrict__ y, const float* __restrict__ g,
    const float* __restrict__ be, float* __restrict__ o)
{
    const int row = blockIdx.x;
    const float* x = y + (size_t)row * D_MODEL;
    const int t = threadIdx.x;
    float v0 = x[t], v1 = x[t + 256], v2 = x[t + 512];
    float s = v0 + v1 + v2;
    float q = v0 * v0 + v1 * v1 + v2 * v2;
#pragma unroll
    for (int off = 16; off; off >>= 1) {
        s += __shfl_xor_sync(0xffffffffu, s, off);
        q += __shfl_xor_sync(0xffffffffu, q, off);
    }
    __shared__ float ss[8], sq[8];
    __shared__ float s_mu, s_inv;
    int w = t >> 5, l = t & 31;
    if (l == 0) { ss[w] = s; sq[w] = q; }
    __syncthreads();
    if (t == 0) {
        float S = 0.f, Q = 0.f;
#pragma unroll
        for (int i = 0; i < 8; ++i) { S += ss[i]; Q += sq[i]; }
        float mu = S * (1.0f / D_MODEL);
        float var = Q * (1.0f / D_MODEL) - mu * mu;
        s_mu = mu;
        s_inv = rsqrtf(var + 1e-5f);
    }
    __syncthreads();
    float mu = s_mu, inv = s_inv;
    float* op = o + (size_t)row * D_MODEL;
    op[t]       = (v0 - mu) * inv * g[t]       + be[t];
    op[t + 256] = (v1 - mu) * inv * g[t + 256] + be[t + 256];
    op[t + 512] = (v2 - mu) * inv * g[t + 512] + be[t + 512];
}

// ------------------------- launch ----------------------------------------
extern "C" void kernel_launch(void* const* d_in, const int* in_sizes, int n_in,
                              void* d_out, int out_size)
{
    const float* src   = (const float*)d_in[0];
    const float* w_qkv = (const float*)d_in[1];
    const float* b_qkv = (const float*)d_in[2];
    const float* w_out = (const float*)d_in[3];
    const float* b_out = (const float*)d_in[4];
    const float* w1    = (const float*)d_in[5];
    const float* b1    = (const float*)d_in[6];
    const float* w2    = (const float*)d_in[7];
    const float* b2    = (const float*)d_in[8];
    const float* ln1w  = (const float*)d_in[9];
    const float* ln1b  = (const float*)d_in[10];
    const float* ln2w  = (const float*)d_in[11];
    const float* ln2b  = (const float*)d_in[12];
    float* out = (float*)d_out;

    float *qkv, *ctx, *y, *x, *hb;
    cudaGetSymbolAddress((void**)&qkv, g_qkv);
    cudaGetSymbolAddress((void**)&ctx, g_ctx);
    cudaGetSymbolAddress((void**)&y,   g_y);
    cudaGetSymbolAddress((void**)&x,   g_x);
    cudaGetSymbolAddress((void**)&hb,  g_h);

    cudaFuncSetAttribute(attn_tc,
                         cudaFuncAttributeMaxDynamicSharedMemorySize, ATTN_SMEM);

    dim3 thr(256);
    // 1) QKV projection
    gemm_tc<<<dim3(D3 / 128, MROWS / 128), thr>>>(
        src, w_qkv, b_qkv, nullptr, qkv, MROWS, D3, D_MODEL, 0);
    // 2) flash attention
    attn_tc<<<dim3(SEQ / 64, BATCH * NHEAD), thr, ATTN_SMEM>>>(qkv, ctx);
    // 3) out projection + residual(src)
    gemm_tc<<<dim3(D_MODEL / 128, MROWS / 128), thr>>>(
        ctx, w_out, b_out, src, y, MROWS, D_MODEL, D_MODEL, 0);
    // 4) LN1
    ln_kernel<<<MROWS, 256>>>(y, ln1w, ln1b, x);
    // 5) FFN1 + relu
    gemm_tc<<<dim3(DFF / 128, MROWS / 128), thr>>>(
        x, w1, b1, nullptr, hb, MROWS, DFF, D_MODEL, 1);
    // 6) FFN2 + residual(x)
    gemm_tc<<<dim3(D_MODEL / 128, MROWS / 128), thr>>>(
        hb, w2, b2, x, y, MROWS, D_MODEL, DFF, 0);
    // 7) LN2
    ln_kernel<<<MROWS, 256>>>(y, ln2w, ln2b, out);
}